// round 4
// baseline (speedup 1.0000x reference)
#include <cuda_runtime.h>

#define C     256
#define H     128
#define W     128
#define GK2   72
#define KK    9
#define CPG   32            // C / GROUP
#define N_MAX 32
#define BN_EPS 1e-5f
#define CHUNK 2             // samples per chunk (32MB of x — fits L2 with write stream)

// scratch (no allocations allowed)
__device__ float g_pooled[N_MAX * C];
__device__ float g_wk[N_MAX * GK2];
__device__ unsigned g_cnt[N_MAX];   // zero-init; reset by last block each use

// ---------------------------------------------------------------------------
// Kernel 1: global average pool + (last block per sample) weight MLP.
// One block per (n,c) plane. Plane means are block-local -> deterministic.
// ---------------------------------------------------------------------------
__global__ __launch_bounds__(256) void pool_weight_kernel(
    const float* __restrict__ x,
    const float* __restrict__ conv_w, const float* __restrict__ gate_w,
    const float* __restrict__ gamma,  const float* __restrict__ beta,
    const float* __restrict__ mean,   const float* __restrict__ var,
    int base_plane) {
    int plane = base_plane + blockIdx.x;
    int nid   = plane / C;
    const float4* p = (const float4*)(x + (size_t)plane * (H * W));
    float s = 0.f;
#pragma unroll 4
    for (int i = threadIdx.x; i < (H * W) / 4; i += 256) {
        float4 v = p[i];
        s += (v.x + v.y) + (v.z + v.w);
    }
#pragma unroll
    for (int o = 16; o; o >>= 1) s += __shfl_down_sync(0xffffffffu, s, o);
    __shared__ float ws[8];
    __shared__ int   s_last;
    int warp = threadIdx.x >> 5, lane = threadIdx.x & 31;
    if (lane == 0) ws[warp] = s;
    __syncthreads();
    if (threadIdx.x == 0) {
        float t = 0.f;
#pragma unroll
        for (int i = 0; i < 8; ++i) t += ws[i];
        g_pooled[plane] = t * (1.0f / (H * W));
        __threadfence();
        s_last = (atomicAdd(&g_cnt[nid], 1u) == C - 1);
    }
    __syncthreads();
    if (!s_last) return;

    // ---- last block of this sample: compute the 72 softmax weights ----
    __threadfence();
    __shared__ float sp[C];
    __shared__ float slf[GK2];
    __shared__ float sbn[GK2];
    int t = threadIdx.x;
    sp[t] = g_pooled[nid * C + t];
    __syncthreads();

    // slf = pooled @ conv_w^T : warp w computes outputs w*9 .. w*9+8,
    // 32 lanes split the 256-dim dot (8 elems each) + shfl reduce.
#pragma unroll
    for (int o = 0; o < KK; ++o) {
        int tt = warp * KK + o;
        const float4* cw4 = (const float4*)(conv_w + tt * C);
        float4 a = cw4[lane * 2], b = cw4[lane * 2 + 1];
        int k0 = lane * 8;
        float acc = a.x * sp[k0] + a.y * sp[k0 + 1] + a.z * sp[k0 + 2] + a.w * sp[k0 + 3]
                  + b.x * sp[k0 + 4] + b.y * sp[k0 + 5] + b.z * sp[k0 + 6] + b.w * sp[k0 + 7];
#pragma unroll
        for (int off = 16; off; off >>= 1) acc += __shfl_down_sync(0xffffffffu, acc, off);
        if (lane == 0) slf[tt] = acc;
    }
    __syncthreads();
    if (t < GK2) {
        const float* gr = gate_w + t * GK2;
        float acc = 0.f;
#pragma unroll 8
        for (int k = 0; k < GK2; ++k) acc = fmaf(slf[k], gr[k], acc);
        float v = slf[t];
        float gated = v * (1.0f / (1.0f + expf(-acc)));
        sbn[t] = (gated - mean[t]) * (gamma[t] * rsqrtf(var[t] + BN_EPS)) + beta[t];
    }
    __syncthreads();
    if (t < GK2) {
        int g = t / KK;
        float mx = -1e30f;
#pragma unroll
        for (int k = 0; k < KK; ++k) mx = fmaxf(mx, sbn[g * KK + k]);
        float ssum = 0.f;
#pragma unroll
        for (int k = 0; k < KK; ++k) ssum += expf(sbn[g * KK + k] - mx);
        g_wk[nid * GK2 + t] = expf(sbn[t] - mx) / ssum;
    }
    if (threadIdx.x == 0) g_cnt[nid] = 0;   // reset for next graph replay
}

// ---------------------------------------------------------------------------
// Kernel 2: reflect-padded 3x3 weighted average + residual.
// One block per (n,c) plane; warp = full 128-wide row via 32x float4.
// Rolling 3-row register window + 1-row software prefetch; x reads hit L2
// (same chunk as pool); stores are streaming (evict-first).
// ---------------------------------------------------------------------------
struct RowT { float4 v; float L, R; };

__device__ __forceinline__ int reflect_row(int r) {
    return (r <= H - 1) ? r : 2 * (H - 1) - r;
}

__global__ __launch_bounds__(256) void stencil_kernel(
    const float* __restrict__ x, float* __restrict__ out, long long half,
    int base_plane) {
    int plane = base_plane + blockIdx.x;
    int n  = plane / C;
    int ch = plane - n * C;
    int g  = ch / CPG;
    const float* wp = &g_wk[n * GK2 + g * KK];
    float w0 = wp[0], w1 = wp[1], w2 = wp[2];
    float w3 = wp[3], w4 = wp[4], w5 = wp[5];
    float w6 = wp[6], w7 = wp[7], w8 = wp[8];

    const float4* in4 = (const float4*)(x + (size_t)plane * (H * W));
    float4* lo4 = (float4*)out + (size_t)plane * (H * W / 4);
    float4* hi4 = (float4*)(out + half) + (size_t)plane * (H * W / 4);

    int warp = threadIdx.x >> 5, lane = threadIdx.x & 31;
    int y0 = warp * 16;

    auto raw = [&](int y) { return __ldcs(&in4[y * (W / 4) + lane]); };
    auto mk = [&](float4 v) {
        RowT r; r.v = v;
        r.L = __shfl_up_sync(0xffffffffu, v.w, 1);
        r.R = __shfl_down_sync(0xffffffffu, v.x, 1);
        if (lane == 0)  r.L = v.y;   // reflect col -1 -> col 1
        if (lane == 31) r.R = v.z;   // reflect col W -> col W-2
        return r;
    };

    RowT pm = mk(raw(y0 == 0 ? 1 : y0 - 1));     // reflect row -1 -> row 1
    RowT cm = mk(raw(y0));
    float4 n_raw = raw(reflect_row(y0 + 1));

#pragma unroll 4
    for (int y = y0; y < y0 + 16; ++y) {
        float4 f_raw = raw(reflect_row(y + 2));  // prefetch next-next row
        RowT nx = mk(n_raw);
        float4 a;
        a.x = w0 * pm.L   + w1 * pm.v.x + w2 * pm.v.y
            + w3 * cm.L   + w4 * cm.v.x + w5 * cm.v.y
            + w6 * nx.L   + w7 * nx.v.x + w8 * nx.v.y;
        a.y = w0 * pm.v.x + w1 * pm.v.y + w2 * pm.v.z
            + w3 * cm.v.x + w4 * cm.v.y + w5 * cm.v.z
            + w6 * nx.v.x + w7 * nx.v.y + w8 * nx.v.z;
        a.z = w0 * pm.v.y + w1 * pm.v.z + w2 * pm.v.w
            + w3 * cm.v.y + w4 * cm.v.z + w5 * cm.v.w
            + w6 * nx.v.y + w7 * nx.v.z + w8 * nx.v.w;
        a.w = w0 * pm.v.z + w1 * pm.v.w + w2 * pm.R
            + w3 * cm.v.z + w4 * cm.v.w + w5 * cm.R
            + w6 * nx.v.z + w7 * nx.v.w + w8 * nx.R;
        int o = y * (W / 4) + lane;
        __stcs(&lo4[o], a);
        float4 hv;
        hv.x = cm.v.x - a.x;
        hv.y = cm.v.y - a.y;
        hv.z = cm.v.z - a.z;
        hv.w = cm.v.w - a.w;
        __stcs(&hi4[o], hv);
        pm = cm;
        cm = nx;
        n_raw = f_raw;
    }
}

// ---------------------------------------------------------------------------
extern "C" void kernel_launch(void* const* d_in, const int* in_sizes, int n_in,
                              void* d_out, int out_size) {
    const float* x      = (const float*)d_in[0];
    const float* conv_w = (const float*)d_in[1];
    const float* gate_w = (const float*)d_in[2];
    const float* gamma  = (const float*)d_in[3];
    const float* beta   = (const float*)d_in[4];
    const float* mean   = (const float*)d_in[5];
    const float* var    = (const float*)d_in[6];
    int n = in_sizes[0] / (C * H * W);
    long long half = (long long)out_size / 2;

    for (int s = 0; s < n; s += CHUNK) {
        int ns = (n - s < CHUNK) ? (n - s) : CHUNK;
        int base = s * C;
        pool_weight_kernel<<<ns * C, 256>>>(x, conv_w, gate_w, gamma, beta,
                                            mean, var, base);
        stencil_kernel<<<ns * C, 256>>>(x, (float*)d_out, half, base);
    }
}

// round 7
// speedup vs baseline: 1.0463x; 1.0463x over previous
#include <cuda_runtime.h>

#define C     256
#define H     128
#define W     128
#define GK2   72
#define KK    9
#define CPG   32            // C / GROUP
#define N_MAX 32
#define BN_EPS 1e-5f
#define CHUNK 2             // samples per chunk (32MB x + 64MB writes fits L2)

// scratch (no allocations allowed)
__device__ float g_pooled[N_MAX * C];
__device__ float g_wk[N_MAX * GK2];
__device__ unsigned g_cnt[N_MAX];   // zero-init; reset by last block each use

// ---------------------------------------------------------------------------
// Pool path: global average pool of one (n,c) plane; the last finishing block
// of each sample computes the 72 softmax weights (MLP+gate+BN+softmax).
// ---------------------------------------------------------------------------
__device__ __forceinline__ void pool_path(
    const float* __restrict__ x,
    const float* __restrict__ conv_w, const float* __restrict__ gate_w,
    const float* __restrict__ gamma,  const float* __restrict__ beta,
    const float* __restrict__ mean,   const float* __restrict__ var,
    int plane) {
    int nid = plane / C;
    const float4* p = (const float4*)(x + (size_t)plane * (H * W));
    float s = 0.f;
#pragma unroll 4
    for (int i = threadIdx.x; i < (H * W) / 4; i += 256) {
        float4 v = p[i];
        s += (v.x + v.y) + (v.z + v.w);
    }
#pragma unroll
    for (int o = 16; o; o >>= 1) s += __shfl_down_sync(0xffffffffu, s, o);
    __shared__ float ws[8];
    __shared__ int   s_last;
    int warp = threadIdx.x >> 5, lane = threadIdx.x & 31;
    if (lane == 0) ws[warp] = s;
    __syncthreads();
    if (threadIdx.x == 0) {
        float t = 0.f;
#pragma unroll
        for (int i = 0; i < 8; ++i) t += ws[i];
        g_pooled[plane] = t * (1.0f / (H * W));
        __threadfence();
        s_last = (atomicAdd(&g_cnt[nid], 1u) == C - 1);
    }
    __syncthreads();
    if (!s_last) return;

    // ---- last block of this sample: compute the 72 softmax weights ----
    __threadfence();
    __shared__ float sp[C];
    __shared__ float slf[GK2];
    __shared__ float sbn[GK2];
    int t = threadIdx.x;
    sp[t] = g_pooled[nid * C + t];
    __syncthreads();

    // slf = pooled @ conv_w^T : warp w computes outputs w*9 .. w*9+8.
#pragma unroll
    for (int o = 0; o < KK; ++o) {
        int tt = warp * KK + o;
        const float4* cw4 = (const float4*)(conv_w + tt * C);
        float4 a = cw4[lane * 2], b = cw4[lane * 2 + 1];
        int k0 = lane * 8;
        float acc = a.x * sp[k0] + a.y * sp[k0 + 1] + a.z * sp[k0 + 2] + a.w * sp[k0 + 3]
                  + b.x * sp[k0 + 4] + b.y * sp[k0 + 5] + b.z * sp[k0 + 6] + b.w * sp[k0 + 7];
#pragma unroll
        for (int off = 16; off; off >>= 1) acc += __shfl_down_sync(0xffffffffu, acc, off);
        if (lane == 0) slf[tt] = acc;
    }
    __syncthreads();
    if (t < GK2) {
        const float* gr = gate_w + t * GK2;
        float acc = 0.f;
#pragma unroll 8
        for (int k = 0; k < GK2; ++k) acc = fmaf(slf[k], gr[k], acc);
        float v = slf[t];
        float gated = v * (1.0f / (1.0f + expf(-acc)));
        sbn[t] = (gated - mean[t]) * (gamma[t] * rsqrtf(var[t] + BN_EPS)) + beta[t];
    }
    __syncthreads();
    if (t < GK2) {
        int g = t / KK;
        float mx = -1e30f;
#pragma unroll
        for (int k = 0; k < KK; ++k) mx = fmaxf(mx, sbn[g * KK + k]);
        float ssum = 0.f;
#pragma unroll
        for (int k = 0; k < KK; ++k) ssum += expf(sbn[g * KK + k] - mx);
        g_wk[nid * GK2 + t] = expf(sbn[t] - mx) / ssum;
    }
    if (threadIdx.x == 0) g_cnt[nid] = 0;   // reset for next graph replay
}

// ---------------------------------------------------------------------------
// Stencil path: reflect-padded 3x3 weighted average + residual for one plane.
// Warp = full 128-wide row (32 x float4); rolling 3-row window + 1-row
// prefetch; reads stream from L2 (pooled in the previous launch); stores
// evict-first so the write stream does not evict x from L2.
// ---------------------------------------------------------------------------
struct RowT { float4 v; float L, R; };

__device__ __forceinline__ int reflect_row(int r) {
    return (r <= H - 1) ? r : 2 * (H - 1) - r;
}

__device__ __forceinline__ void stencil_path(
    const float* __restrict__ x, float* __restrict__ out, long long half,
    int plane) {
    int n  = plane / C;
    int ch = plane - n * C;
    int g  = ch / CPG;
    const float* wp = &g_wk[n * GK2 + g * KK];
    float w0 = wp[0], w1 = wp[1], w2 = wp[2];
    float w3 = wp[3], w4 = wp[4], w5 = wp[5];
    float w6 = wp[6], w7 = wp[7], w8 = wp[8];

    const float4* in4 = (const float4*)(x + (size_t)plane * (H * W));
    float4* lo4 = (float4*)out + (size_t)plane * (H * W / 4);
    float4* hi4 = (float4*)(out + half) + (size_t)plane * (H * W / 4);

    int warp = threadIdx.x >> 5, lane = threadIdx.x & 31;
    int y0 = warp * 16;

    auto raw = [&](int y) { return __ldcs(&in4[y * (W / 4) + lane]); };
    auto mk = [&](float4 v) {
        RowT r; r.v = v;
        r.L = __shfl_up_sync(0xffffffffu, v.w, 1);
        r.R = __shfl_down_sync(0xffffffffu, v.x, 1);
        if (lane == 0)  r.L = v.y;   // reflect col -1 -> col 1
        if (lane == 31) r.R = v.z;   // reflect col W -> col W-2
        return r;
    };

    RowT pm = mk(raw(y0 == 0 ? 1 : y0 - 1));     // reflect row -1 -> row 1
    RowT cm = mk(raw(y0));
    float4 n_raw = raw(reflect_row(y0 + 1));

#pragma unroll 4
    for (int y = y0; y < y0 + 16; ++y) {
        float4 f_raw = raw(reflect_row(y + 2));  // prefetch next-next row
        RowT nx = mk(n_raw);
        float4 a;
        a.x = w0 * pm.L   + w1 * pm.v.x + w2 * pm.v.y
            + w3 * cm.L   + w4 * cm.v.x + w5 * cm.v.y
            + w6 * nx.L   + w7 * nx.v.x + w8 * nx.v.y;
        a.y = w0 * pm.v.x + w1 * pm.v.y + w2 * pm.v.z
            + w3 * cm.v.x + w4 * cm.v.y + w5 * cm.v.z
            + w6 * nx.v.x + w7 * nx.v.y + w8 * nx.v.z;
        a.z = w0 * pm.v.y + w1 * pm.v.z + w2 * pm.v.w
            + w3 * cm.v.y + w4 * cm.v.z + w5 * cm.v.w
            + w6 * nx.v.y + w7 * nx.v.z + w8 * nx.v.w;
        a.w = w0 * pm.v.z + w1 * pm.v.w + w2 * pm.R
            + w3 * cm.v.z + w4 * cm.v.w + w5 * cm.R
            + w6 * nx.v.z + w7 * nx.v.w + w8 * nx.R;
        int o = y * (W / 4) + lane;
        __stcs(&lo4[o], a);
        float4 hv;
        hv.x = cm.v.x - a.x;
        hv.y = cm.v.y - a.y;
        hv.z = cm.v.z - a.z;
        hv.w = cm.v.w - a.w;
        __stcs(&hi4[o], hv);
        pm = cm;
        cm = nx;
        n_raw = f_raw;
    }
}

// ---------------------------------------------------------------------------
// Fused launch: pool blocks for chunk k interleaved with stencil blocks for
// chunk k-1 in one grid. Roles are independent within a launch; stencil
// consumes weights produced by the PREVIOUS launch's pool blocks (ordered by
// the stream). Pairwise interleave mixes the two memory streams chip-wide.
// ---------------------------------------------------------------------------
__global__ __launch_bounds__(256) void fused_kernel(
    const float* __restrict__ x,
    const float* __restrict__ conv_w, const float* __restrict__ gate_w,
    const float* __restrict__ gamma,  const float* __restrict__ beta,
    const float* __restrict__ mean,   const float* __restrict__ var,
    float* __restrict__ out, long long half,
    int pool_base, int n_pool, int st_base, int n_st) {
    int m = n_pool < n_st ? n_pool : n_st;
    int bid = blockIdx.x;
    int is_pool, idx;
    if (bid < 2 * m) { is_pool = bid & 1; idx = bid >> 1; }
    else             { is_pool = (n_pool > n_st); idx = bid - m; }
    if (is_pool)
        pool_path(x, conv_w, gate_w, gamma, beta, mean, var, pool_base + idx);
    else
        stencil_path(x, out, half, st_base + idx);
}

// ---------------------------------------------------------------------------
extern "C" void kernel_launch(void* const* d_in, const int* in_sizes, int n_in,
                              void* d_out, int out_size) {
    const float* x      = (const float*)d_in[0];
    const float* conv_w = (const float*)d_in[1];
    const float* gate_w = (const float*)d_in[2];
    const float* gamma  = (const float*)d_in[3];
    const float* beta   = (const float*)d_in[4];
    const float* mean   = (const float*)d_in[5];
    const float* var    = (const float*)d_in[6];
    int n = in_sizes[0] / (C * H * W);
    long long half = (long long)out_size / 2;

    int nchunks = (n + CHUNK - 1) / CHUNK;
    for (int k = 0; k <= nchunks; ++k) {
        int np = 0, pool_base = 0, ns = 0, st_base = 0;
        if (k < nchunks) {
            int s = k * CHUNK;
            np = ((n - s < CHUNK) ? (n - s) : CHUNK) * C;
            pool_base = s * C;
        }
        if (k >= 1) {
            int s = (k - 1) * CHUNK;
            ns = ((n - s < CHUNK) ? (n - s) : CHUNK) * C;
            st_base = s * C;
        }
        if (np + ns == 0) continue;
        fused_kernel<<<np + ns, 256>>>(x, conv_w, gate_w, gamma, beta, mean,
                                       var, (float*)d_out, half,
                                       pool_base, np, st_base, ns);
    }
}

// round 8
// speedup vs baseline: 1.0501x; 1.0036x over previous
#include <cuda_runtime.h>

#define C     256
#define H     128
#define W     128
#define GK2   72
#define KK    9
#define CPG   32            // C / GROUP
#define N_MAX 32
#define BN_EPS 1e-5f

// scratch (no allocations allowed); zero-init, restored to zero each run
__device__ float g_pooled[N_MAX * C];
__device__ float g_wk[N_MAX * GK2];
__device__ unsigned g_cnt[N_MAX];            // pool-block completion counter
__device__ unsigned g_stcnt[N_MAX];          // stencil-block completion counter
__device__ volatile unsigned g_ready[N_MAX]; // per-sample "weights ready" flag

// ---------------------------------------------------------------------------
// Pool path: global average pool of one (n,c) plane; the last finishing block
// of each sample computes the 72 softmax weights and publishes g_ready[n].
// Plain (caching) loads: keep x in L2 for the stencil consumer.
// ---------------------------------------------------------------------------
__device__ __forceinline__ void pool_path(
    const float* __restrict__ x,
    const float* __restrict__ conv_w, const float* __restrict__ gate_w,
    const float* __restrict__ gamma,  const float* __restrict__ beta,
    const float* __restrict__ mean,   const float* __restrict__ var,
    int plane) {
    int nid = plane / C;
    const float4* p = (const float4*)(x + (size_t)plane * (H * W));
    float s = 0.f;
#pragma unroll 4
    for (int i = threadIdx.x; i < (H * W) / 4; i += 256) {
        float4 v = p[i];
        s += (v.x + v.y) + (v.z + v.w);
    }
#pragma unroll
    for (int o = 16; o; o >>= 1) s += __shfl_down_sync(0xffffffffu, s, o);
    __shared__ float ws[8];
    __shared__ int   s_last;
    int warp = threadIdx.x >> 5, lane = threadIdx.x & 31;
    if (lane == 0) ws[warp] = s;
    __syncthreads();
    if (threadIdx.x == 0) {
        float t = 0.f;
#pragma unroll
        for (int i = 0; i < 8; ++i) t += ws[i];
        g_pooled[plane] = t * (1.0f / (H * W));
        __threadfence();
        s_last = (atomicAdd(&g_cnt[nid], 1u) == C - 1);
    }
    __syncthreads();
    if (!s_last) return;

    // ---- last block of this sample: compute the 72 softmax weights ----
    __threadfence();
    __shared__ float sp[C];
    __shared__ float slf[GK2];
    __shared__ float sbn[GK2];
    int t = threadIdx.x;
    sp[t] = g_pooled[nid * C + t];
    __syncthreads();

    // slf = pooled @ conv_w^T : warp w computes outputs w*9 .. w*9+8.
#pragma unroll
    for (int o = 0; o < KK; ++o) {
        int tt = warp * KK + o;
        const float4* cw4 = (const float4*)(conv_w + tt * C);
        float4 a = cw4[lane * 2], b = cw4[lane * 2 + 1];
        int k0 = lane * 8;
        float acc = a.x * sp[k0] + a.y * sp[k0 + 1] + a.z * sp[k0 + 2] + a.w * sp[k0 + 3]
                  + b.x * sp[k0 + 4] + b.y * sp[k0 + 5] + b.z * sp[k0 + 6] + b.w * sp[k0 + 7];
#pragma unroll
        for (int off = 16; off; off >>= 1) acc += __shfl_down_sync(0xffffffffu, acc, off);
        if (lane == 0) slf[tt] = acc;
    }
    __syncthreads();
    if (t < GK2) {
        const float* gr = gate_w + t * GK2;
        float acc = 0.f;
#pragma unroll 8
        for (int k = 0; k < GK2; ++k) acc = fmaf(slf[k], gr[k], acc);
        float v = slf[t];
        float gated = v * (1.0f / (1.0f + expf(-acc)));
        sbn[t] = (gated - mean[t]) * (gamma[t] * rsqrtf(var[t] + BN_EPS)) + beta[t];
    }
    __syncthreads();
    if (t < GK2) {
        int g = t / KK;
        float mx = -1e30f;
#pragma unroll
        for (int k = 0; k < KK; ++k) mx = fmaxf(mx, sbn[g * KK + k]);
        float ssum = 0.f;
#pragma unroll
        for (int k = 0; k < KK; ++k) ssum += expf(sbn[g * KK + k] - mx);
        g_wk[nid * GK2 + t] = expf(sbn[t] - mx) / ssum;
    }
    __syncthreads();
    if (threadIdx.x == 0) {
        g_cnt[nid] = 0;          // reset for next graph replay
        __threadfence();
        g_ready[nid] = 1u;       // publish: weights visible to stencil blocks
    }
}

// ---------------------------------------------------------------------------
// Stencil path: reflect-padded 3x3 weighted average + residual for one plane.
// Waits on g_ready[n] (set by this sample's pool blocks, which all have lower
// block ids -> guaranteed forward progress, no deadlock). x reads are L2-hot
// (pooled ~1 sample earlier); __ldcs marks them last-use; stores evict-first.
// ---------------------------------------------------------------------------
struct RowT { float4 v; float L, R; };

__device__ __forceinline__ int reflect_row(int r) {
    return (r <= H - 1) ? r : 2 * (H - 1) - r;
}

__device__ __forceinline__ void stencil_path(
    const float* __restrict__ x, float* __restrict__ out, long long half,
    int plane) {
    int n  = plane / C;
    int ch = plane - n * C;
    int g  = ch / CPG;

    // wait for this sample's weights
    if (threadIdx.x == 0) {
        while (g_ready[n] == 0u) __nanosleep(128);
        __threadfence();   // acquire: order g_wk reads after flag observation
    }
    __syncthreads();

    const float* wp = &g_wk[n * GK2 + g * KK];
    float w0 = __ldcg(wp + 0), w1 = __ldcg(wp + 1), w2 = __ldcg(wp + 2);
    float w3 = __ldcg(wp + 3), w4 = __ldcg(wp + 4), w5 = __ldcg(wp + 5);
    float w6 = __ldcg(wp + 6), w7 = __ldcg(wp + 7), w8 = __ldcg(wp + 8);

    const float4* in4 = (const float4*)(x + (size_t)plane * (H * W));
    float4* lo4 = (float4*)out + (size_t)plane * (H * W / 4);
    float4* hi4 = (float4*)(out + half) + (size_t)plane * (H * W / 4);

    int warp = threadIdx.x >> 5, lane = threadIdx.x & 31;
    int y0 = warp * 16;

    auto raw = [&](int y) { return __ldcs(&in4[y * (W / 4) + lane]); };
    auto mk = [&](float4 v) {
        RowT r; r.v = v;
        r.L = __shfl_up_sync(0xffffffffu, v.w, 1);
        r.R = __shfl_down_sync(0xffffffffu, v.x, 1);
        if (lane == 0)  r.L = v.y;   // reflect col -1 -> col 1
        if (lane == 31) r.R = v.z;   // reflect col W -> col W-2
        return r;
    };

    RowT pm = mk(raw(y0 == 0 ? 1 : y0 - 1));     // reflect row -1 -> row 1
    RowT cm = mk(raw(y0));
    float4 n_raw = raw(reflect_row(y0 + 1));

#pragma unroll 4
    for (int y = y0; y < y0 + 16; ++y) {
        float4 f_raw = raw(reflect_row(y + 2));  // prefetch next-next row
        RowT nx = mk(n_raw);
        float4 a;
        a.x = w0 * pm.L   + w1 * pm.v.x + w2 * pm.v.y
            + w3 * cm.L   + w4 * cm.v.x + w5 * cm.v.y
            + w6 * nx.L   + w7 * nx.v.x + w8 * nx.v.y;
        a.y = w0 * pm.v.x + w1 * pm.v.y + w2 * pm.v.z
            + w3 * cm.v.x + w4 * cm.v.y + w5 * cm.v.z
            + w6 * nx.v.x + w7 * nx.v.y + w8 * nx.v.z;
        a.z = w0 * pm.v.y + w1 * pm.v.z + w2 * pm.v.w
            + w3 * cm.v.y + w4 * cm.v.z + w5 * cm.v.w
            + w6 * nx.v.y + w7 * nx.v.z + w8 * nx.v.w;
        a.w = w0 * pm.v.z + w1 * pm.v.w + w2 * pm.R
            + w3 * cm.v.z + w4 * cm.v.w + w5 * cm.R
            + w6 * nx.v.z + w7 * nx.v.w + w8 * nx.R;
        int o = y * (W / 4) + lane;
        __stcs(&lo4[o], a);
        float4 hv;
        hv.x = cm.v.x - a.x;
        hv.y = cm.v.y - a.y;
        hv.z = cm.v.z - a.z;
        hv.w = cm.v.w - a.w;
        __stcs(&hi4[o], hv);
        pm = cm;
        cm = nx;
        n_raw = f_raw;
    }

    // last stencil block of the sample resets the flag (graph-replay safety)
    __syncthreads();
    if (threadIdx.x == 0) {
        if (atomicAdd(&g_stcnt[n], 1u) == C - 1) {
            g_stcnt[n] = 0;
            g_ready[n] = 0u;
        }
    }
}

// ---------------------------------------------------------------------------
// Single-launch software pipeline over the whole batch.
// Block order: [pool s0] [pool s1 | stencil s0]... [stencil s(n-1)].
// Pool blocks of sample s always have lower bids than stencil blocks of s.
// ---------------------------------------------------------------------------
__global__ __launch_bounds__(256, 5) void pipeline_kernel(
    const float* __restrict__ x,
    const float* __restrict__ conv_w, const float* __restrict__ gate_w,
    const float* __restrict__ gamma,  const float* __restrict__ beta,
    const float* __restrict__ mean,   const float* __restrict__ var,
    float* __restrict__ out, long long half, int n) {
    int bid = blockIdx.x;
    int role, plane;
    if (bid < C) {                               // leading pool segment (s0)
        role = 0; plane = bid;
    } else {
        int q = bid - C;
        int mid = (n - 1) * 2 * C;
        if (q < mid) {                           // interleaved middle segments
            int seg = q / (2 * C);
            int r   = q - seg * 2 * C;
            if ((r & 1) == 0) { role = 0; plane = (seg + 1) * C + (r >> 1); }
            else              { role = 1; plane = seg * C + (r >> 1); }
        } else {                                 // trailing stencil segment
            role = 1; plane = (n - 1) * C + (q - mid);
        }
    }
    if (role == 0)
        pool_path(x, conv_w, gate_w, gamma, beta, mean, var, plane);
    else
        stencil_path(x, out, half, plane);
}

// ---------------------------------------------------------------------------
extern "C" void kernel_launch(void* const* d_in, const int* in_sizes, int n_in,
                              void* d_out, int out_size) {
    const float* x      = (const float*)d_in[0];
    const float* conv_w = (const float*)d_in[1];
    const float* gate_w = (const float*)d_in[2];
    const float* gamma  = (const float*)d_in[3];
    const float* beta   = (const float*)d_in[4];
    const float* mean   = (const float*)d_in[5];
    const float* var    = (const float*)d_in[6];
    int n = in_sizes[0] / (C * H * W);
    long long half = (long long)out_size / 2;

    pipeline_kernel<<<2 * n * C, 256>>>(x, conv_w, gate_w, gamma, beta, mean,
                                        var, (float*)d_out, half, n);
}

// round 9
// speedup vs baseline: 1.0797x; 1.0281x over previous
#include <cuda_runtime.h>

#define C     256
#define H     128
#define W     128
#define GK2   72
#define KK    9
#define CPG   32            // C / GROUP
#define N_MAX 32
#define BN_EPS 1e-5f

// scratch (no allocations allowed); zero-init, restored to zero each run
__device__ float g_pooled[N_MAX * C];
__device__ float g_wk[N_MAX * GK2];
__device__ unsigned g_cnt[N_MAX];            // pool-block completion counter
__device__ unsigned g_stcnt[N_MAX];          // stencil-block completion counter
__device__ volatile unsigned g_ready[N_MAX]; // per-sample "weights ready" flag

// ---------------------------------------------------------------------------
// Pool path: global average pool of one (n,c) plane; the last finishing block
// of each sample computes the 72 softmax weights and publishes g_ready[n].
// ---------------------------------------------------------------------------
__device__ __forceinline__ void pool_path(
    const float* __restrict__ x,
    const float* __restrict__ conv_w, const float* __restrict__ gate_w,
    const float* __restrict__ gamma,  const float* __restrict__ beta,
    const float* __restrict__ mean,   const float* __restrict__ var,
    int plane) {
    int nid = plane / C;
    const float4* p = (const float4*)(x + (size_t)plane * (H * W));
    float s = 0.f;
#pragma unroll 4
    for (int i = threadIdx.x; i < (H * W) / 4; i += 256) {
        float4 v = p[i];
        s += (v.x + v.y) + (v.z + v.w);
    }
#pragma unroll
    for (int o = 16; o; o >>= 1) s += __shfl_down_sync(0xffffffffu, s, o);
    __shared__ float ws[8];
    __shared__ int   s_last;
    int warp = threadIdx.x >> 5, lane = threadIdx.x & 31;
    if (lane == 0) ws[warp] = s;
    __syncthreads();
    if (threadIdx.x == 0) {
        float t = 0.f;
#pragma unroll
        for (int i = 0; i < 8; ++i) t += ws[i];
        g_pooled[plane] = t * (1.0f / (H * W));
        __threadfence();
        s_last = (atomicAdd(&g_cnt[nid], 1u) == C - 1);
    }
    __syncthreads();
    if (!s_last) return;

    // ---- last block of this sample: compute the 72 softmax weights ----
    __threadfence();
    __shared__ float sp[C];
    __shared__ float slf[GK2];
    __shared__ float sbn[GK2];
    int t = threadIdx.x;
    sp[t] = g_pooled[nid * C + t];
    __syncthreads();

    // slf = pooled @ conv_w^T : warp w computes outputs w*9 .. w*9+8.
#pragma unroll
    for (int o = 0; o < KK; ++o) {
        int tt = warp * KK + o;
        const float4* cw4 = (const float4*)(conv_w + tt * C);
        float4 a = cw4[lane * 2], b = cw4[lane * 2 + 1];
        int k0 = lane * 8;
        float acc = a.x * sp[k0] + a.y * sp[k0 + 1] + a.z * sp[k0 + 2] + a.w * sp[k0 + 3]
                  + b.x * sp[k0 + 4] + b.y * sp[k0 + 5] + b.z * sp[k0 + 6] + b.w * sp[k0 + 7];
#pragma unroll
        for (int off = 16; off; off >>= 1) acc += __shfl_down_sync(0xffffffffu, acc, off);
        if (lane == 0) slf[tt] = acc;
    }
    __syncthreads();
    if (t < GK2) {
        const float* gr = gate_w + t * GK2;
        float acc = 0.f;
#pragma unroll 8
        for (int k = 0; k < GK2; ++k) acc = fmaf(slf[k], gr[k], acc);
        float v = slf[t];
        float gated = v * (1.0f / (1.0f + expf(-acc)));
        sbn[t] = (gated - mean[t]) * (gamma[t] * rsqrtf(var[t] + BN_EPS)) + beta[t];
    }
    __syncthreads();
    if (t < GK2) {
        int g = t / KK;
        float mx = -1e30f;
#pragma unroll
        for (int k = 0; k < KK; ++k) mx = fmaxf(mx, sbn[g * KK + k]);
        float ssum = 0.f;
#pragma unroll
        for (int k = 0; k < KK; ++k) ssum += expf(sbn[g * KK + k] - mx);
        g_wk[nid * GK2 + t] = expf(sbn[t] - mx) / ssum;
    }
    __syncthreads();
    if (threadIdx.x == 0) {
        g_cnt[nid] = 0;          // reset for next graph replay
        __threadfence();
        g_ready[nid] = 1u;       // publish: weights visible to stencil blocks
    }
}

// ---------------------------------------------------------------------------
// Stencil path: reflect-padded 3x3 weighted average + residual for one plane.
// 4-row chunked: issue 4 back-to-back LDG.128 per chunk (MLP=4), 6-row
// register window, then 4 output rows. Waits on g_ready[n] (producers have
// strictly lower block ids -> no deadlock).
// ---------------------------------------------------------------------------
struct RowT { float4 v; float L, R; };

__device__ __forceinline__ int reflect_row(int r) {
    return (r <= H - 1) ? r : 2 * (H - 1) - r;
}

__device__ __forceinline__ void stencil_path(
    const float* __restrict__ x, float* __restrict__ out, long long half,
    int plane) {
    int n  = plane / C;
    int ch = plane - n * C;
    int g  = ch / CPG;

    // wait for this sample's weights
    if (threadIdx.x == 0) {
        while (g_ready[n] == 0u) __nanosleep(128);
        __threadfence();   // acquire: order g_wk reads after flag observation
    }
    __syncthreads();

    const float* wp = &g_wk[n * GK2 + g * KK];
    float w0 = __ldcg(wp + 0), w1 = __ldcg(wp + 1), w2 = __ldcg(wp + 2);
    float w3 = __ldcg(wp + 3), w4 = __ldcg(wp + 4), w5 = __ldcg(wp + 5);
    float w6 = __ldcg(wp + 6), w7 = __ldcg(wp + 7), w8 = __ldcg(wp + 8);

    const float4* in4 = (const float4*)(x + (size_t)plane * (H * W));
    float4* lo4 = (float4*)out + (size_t)plane * (H * W / 4);
    float4* hi4 = (float4*)(out + half) + (size_t)plane * (H * W / 4);

    int warp = threadIdx.x >> 5, lane = threadIdx.x & 31;
    int y0 = warp * 16;

    auto raw = [&](int y) { return __ldcs(&in4[y * (W / 4) + lane]); };
    auto mk = [&](float4 v) {
        RowT r; r.v = v;
        r.L = __shfl_up_sync(0xffffffffu, v.w, 1);
        r.R = __shfl_down_sync(0xffffffffu, v.x, 1);
        if (lane == 0)  r.L = v.y;   // reflect col -1 -> col 1
        if (lane == 31) r.R = v.z;   // reflect col W -> col W-2
        return r;
    };

    RowT r[6];
    r[0] = mk(raw(y0 == 0 ? 1 : y0 - 1));   // reflect row -1 -> row 1
    r[1] = mk(raw(y0));

#pragma unroll
    for (int yc = 0; yc < 16; yc += 4) {
        int yb = y0 + yc;
        // 4 independent loads issued back-to-back (MLP = 4)
        float4 t2 = raw(reflect_row(yb + 1));
        float4 t3 = raw(reflect_row(yb + 2));
        float4 t4 = raw(reflect_row(yb + 3));
        float4 t5 = raw(reflect_row(yb + 4));
        r[2] = mk(t2); r[3] = mk(t3); r[4] = mk(t4); r[5] = mk(t5);
#pragma unroll
        for (int i = 0; i < 4; ++i) {
            const RowT& pm = r[i];
            const RowT& cm = r[i + 1];
            const RowT& nx = r[i + 2];
            float4 a;
            a.x = w0 * pm.L   + w1 * pm.v.x + w2 * pm.v.y
                + w3 * cm.L   + w4 * cm.v.x + w5 * cm.v.y
                + w6 * nx.L   + w7 * nx.v.x + w8 * nx.v.y;
            a.y = w0 * pm.v.x + w1 * pm.v.y + w2 * pm.v.z
                + w3 * cm.v.x + w4 * cm.v.y + w5 * cm.v.z
                + w6 * nx.v.x + w7 * nx.v.y + w8 * nx.v.z;
            a.z = w0 * pm.v.y + w1 * pm.v.z + w2 * pm.v.w
                + w3 * cm.v.y + w4 * cm.v.z + w5 * cm.v.w
                + w6 * nx.v.y + w7 * nx.v.z + w8 * nx.v.w;
            a.w = w0 * pm.v.z + w1 * pm.v.w + w2 * pm.R
                + w3 * cm.v.z + w4 * cm.v.w + w5 * cm.R
                + w6 * nx.v.z + w7 * nx.v.w + w8 * nx.R;
            int o = (yb + i) * (W / 4) + lane;
            __stcs(&lo4[o], a);
            float4 hv;
            hv.x = cm.v.x - a.x;
            hv.y = cm.v.y - a.y;
            hv.z = cm.v.z - a.z;
            hv.w = cm.v.w - a.w;
            __stcs(&hi4[o], hv);
        }
        r[0] = r[4];
        r[1] = r[5];
    }

    // last stencil block of the sample resets the flag (graph-replay safety)
    __syncthreads();
    if (threadIdx.x == 0) {
        if (atomicAdd(&g_stcnt[n], 1u) == C - 1) {
            g_stcnt[n] = 0;
            g_ready[n] = 0u;
        }
    }
}

// ---------------------------------------------------------------------------
// Single-launch software pipeline over the whole batch.
// Block order: [pool s0] [pool s1 | stencil s0]... [stencil s(n-1)].
// Pool blocks of sample s always have lower bids than stencil blocks of s.
// ---------------------------------------------------------------------------
__global__ __launch_bounds__(256, 4) void pipeline_kernel(
    const float* __restrict__ x,
    const float* __restrict__ conv_w, const float* __restrict__ gate_w,
    const float* __restrict__ gamma,  const float* __restrict__ beta,
    const float* __restrict__ mean,   const float* __restrict__ var,
    float* __restrict__ out, long long half, int n) {
    int bid = blockIdx.x;
    int role, plane;
    if (bid < C) {                               // leading pool segment (s0)
        role = 0; plane = bid;
    } else {
        int q = bid - C;
        int mid = (n - 1) * 2 * C;
        if (q < mid) {                           // interleaved middle segments
            int seg = q / (2 * C);
            int r   = q - seg * 2 * C;
            if ((r & 1) == 0) { role = 0; plane = (seg + 1) * C + (r >> 1); }
            else              { role = 1; plane = seg * C + (r >> 1); }
        } else {                                 // trailing stencil segment
            role = 1; plane = (n - 1) * C + (q - mid);
        }
    }
    if (role == 0)
        pool_path(x, conv_w, gate_w, gamma, beta, mean, var, plane);
    else
        stencil_path(x, out, half, plane);
}

// ---------------------------------------------------------------------------
extern "C" void kernel_launch(void* const* d_in, const int* in_sizes, int n_in,
                              void* d_out, int out_size) {
    const float* x      = (const float*)d_in[0];
    const float* conv_w = (const float*)d_in[1];
    const float* gate_w = (const float*)d_in[2];
    const float* gamma  = (const float*)d_in[3];
    const float* beta   = (const float*)d_in[4];
    const float* mean   = (const float*)d_in[5];
    const float* var    = (const float*)d_in[6];
    int n = in_sizes[0] / (C * H * W);
    long long half = (long long)out_size / 2;

    pipeline_kernel<<<2 * n * C, 256>>>(x, conv_w, gate_w, gamma, beta, mean,
                                        var, (float*)d_out, half, n);
}

// round 10
// speedup vs baseline: 1.1583x; 1.0729x over previous
#include <cuda_runtime.h>

#define C     256
#define H     128
#define W     128
#define GK2   72
#define KK    9
#define CPG   32            // C / GROUP
#define N_MAX 32
#define BN_EPS 1e-5f
#define LEAD  2             // pipeline distance in samples (2 waves of blocks)

// scratch (no allocations allowed); zero-init, restored to zero each run
__device__ float g_pooled[N_MAX * C];
__device__ float g_wk[N_MAX * GK2];
__device__ unsigned g_cnt[N_MAX];            // pool-block completion counter
__device__ unsigned g_stcnt[N_MAX];          // stencil-block completion counter
__device__ volatile unsigned g_ready[N_MAX]; // per-sample "weights ready" flag

// ---------------------------------------------------------------------------
// Pool path: global average pool of one (n,c) plane; the last finishing block
// of each sample computes the 72 softmax weights and publishes g_ready[n].
// Plain caching loads: deposit x in L2 for the stencil consumer.
// ---------------------------------------------------------------------------
__device__ __forceinline__ void pool_path(
    const float* __restrict__ x,
    const float* __restrict__ conv_w, const float* __restrict__ gate_w,
    const float* __restrict__ gamma,  const float* __restrict__ beta,
    const float* __restrict__ mean,   const float* __restrict__ var,
    int plane) {
    int nid = plane / C;
    const float4* p = (const float4*)(x + (size_t)plane * (H * W));
    float s = 0.f;
#pragma unroll 4
    for (int i = threadIdx.x; i < (H * W) / 4; i += 256) {
        float4 v = p[i];
        s += (v.x + v.y) + (v.z + v.w);
    }
#pragma unroll
    for (int o = 16; o; o >>= 1) s += __shfl_down_sync(0xffffffffu, s, o);
    __shared__ float ws[8];
    __shared__ int   s_last;
    int warp = threadIdx.x >> 5, lane = threadIdx.x & 31;
    if (lane == 0) ws[warp] = s;
    __syncthreads();
    if (threadIdx.x == 0) {
        float t = 0.f;
#pragma unroll
        for (int i = 0; i < 8; ++i) t += ws[i];
        g_pooled[plane] = t * (1.0f / (H * W));
        __threadfence();
        s_last = (atomicAdd(&g_cnt[nid], 1u) == C - 1);
    }
    __syncthreads();
    if (!s_last) return;

    // ---- last block of this sample: compute the 72 softmax weights ----
    __threadfence();
    __shared__ float sp[C];
    __shared__ float slf[GK2];
    __shared__ float sbn[GK2];
    int t = threadIdx.x;
    sp[t] = g_pooled[nid * C + t];
    __syncthreads();

    // slf = pooled @ conv_w^T : warp w computes outputs w*9 .. w*9+8.
#pragma unroll
    for (int o = 0; o < KK; ++o) {
        int tt = warp * KK + o;
        const float4* cw4 = (const float4*)(conv_w + tt * C);
        float4 a = cw4[lane * 2], b = cw4[lane * 2 + 1];
        int k0 = lane * 8;
        float acc = a.x * sp[k0] + a.y * sp[k0 + 1] + a.z * sp[k0 + 2] + a.w * sp[k0 + 3]
                  + b.x * sp[k0 + 4] + b.y * sp[k0 + 5] + b.z * sp[k0 + 6] + b.w * sp[k0 + 7];
#pragma unroll
        for (int off = 16; off; off >>= 1) acc += __shfl_down_sync(0xffffffffu, acc, off);
        if (lane == 0) slf[tt] = acc;
    }
    __syncthreads();
    if (t < GK2) {
        const float* gr = gate_w + t * GK2;
        float acc = 0.f;
#pragma unroll 8
        for (int k = 0; k < GK2; ++k) acc = fmaf(slf[k], gr[k], acc);
        float v = slf[t];
        float gated = v * (1.0f / (1.0f + expf(-acc)));
        sbn[t] = (gated - mean[t]) * (gamma[t] * rsqrtf(var[t] + BN_EPS)) + beta[t];
    }
    __syncthreads();
    if (t < GK2) {
        int g = t / KK;
        float mx = -1e30f;
#pragma unroll
        for (int k = 0; k < KK; ++k) mx = fmaxf(mx, sbn[g * KK + k]);
        float ssum = 0.f;
#pragma unroll
        for (int k = 0; k < KK; ++k) ssum += expf(sbn[g * KK + k] - mx);
        g_wk[nid * GK2 + t] = expf(sbn[t] - mx) / ssum;
    }
    __syncthreads();
    if (threadIdx.x == 0) {
        g_cnt[nid] = 0;          // reset for next graph replay
        __threadfence();
        g_ready[nid] = 1u;       // publish: weights visible to stencil blocks
    }
}

// ---------------------------------------------------------------------------
// Stencil path: reflect-padded 3x3 weighted average + residual for one plane.
// Rolling 3-row register window + 1-row prefetch (48 regs). Waits on
// g_ready[n]; producers have bids >= 2 segments lower -> flag is nearly
// always already set. x reads are L2-hot; __ldcs last-use; stores evict-first.
// ---------------------------------------------------------------------------
struct RowT { float4 v; float L, R; };

__device__ __forceinline__ int reflect_row(int r) {
    return (r <= H - 1) ? r : 2 * (H - 1) - r;
}

__device__ __forceinline__ void stencil_path(
    const float* __restrict__ x, float* __restrict__ out, long long half,
    int plane) {
    int n  = plane / C;
    int ch = plane - n * C;
    int g  = ch / CPG;

    // wait for this sample's weights (usually already published)
    if (threadIdx.x == 0) {
        while (g_ready[n] == 0u) __nanosleep(64);
        __threadfence();   // acquire: order g_wk reads after flag observation
    }
    __syncthreads();

    const float* wp = &g_wk[n * GK2 + g * KK];
    float w0 = __ldcg(wp + 0), w1 = __ldcg(wp + 1), w2 = __ldcg(wp + 2);
    float w3 = __ldcg(wp + 3), w4 = __ldcg(wp + 4), w5 = __ldcg(wp + 5);
    float w6 = __ldcg(wp + 6), w7 = __ldcg(wp + 7), w8 = __ldcg(wp + 8);

    const float4* in4 = (const float4*)(x + (size_t)plane * (H * W));
    float4* lo4 = (float4*)out + (size_t)plane * (H * W / 4);
    float4* hi4 = (float4*)(out + half) + (size_t)plane * (H * W / 4);

    int warp = threadIdx.x >> 5, lane = threadIdx.x & 31;
    int y0 = warp * 16;

    auto raw = [&](int y) { return __ldcs(&in4[y * (W / 4) + lane]); };
    auto mk = [&](float4 v) {
        RowT r; r.v = v;
        r.L = __shfl_up_sync(0xffffffffu, v.w, 1);
        r.R = __shfl_down_sync(0xffffffffu, v.x, 1);
        if (lane == 0)  r.L = v.y;   // reflect col -1 -> col 1
        if (lane == 31) r.R = v.z;   // reflect col W -> col W-2
        return r;
    };

    RowT pm = mk(raw(y0 == 0 ? 1 : y0 - 1));     // reflect row -1 -> row 1
    RowT cm = mk(raw(y0));
    float4 n_raw = raw(reflect_row(y0 + 1));

#pragma unroll 4
    for (int y = y0; y < y0 + 16; ++y) {
        float4 f_raw = raw(reflect_row(y + 2));  // prefetch next-next row
        RowT nx = mk(n_raw);
        float4 a;
        a.x = w0 * pm.L   + w1 * pm.v.x + w2 * pm.v.y
            + w3 * cm.L   + w4 * cm.v.x + w5 * cm.v.y
            + w6 * nx.L   + w7 * nx.v.x + w8 * nx.v.y;
        a.y = w0 * pm.v.x + w1 * pm.v.y + w2 * pm.v.z
            + w3 * cm.v.x + w4 * cm.v.y + w5 * cm.v.z
            + w6 * nx.v.x + w7 * nx.v.y + w8 * nx.v.z;
        a.z = w0 * pm.v.y + w1 * pm.v.z + w2 * pm.v.w
            + w3 * cm.v.y + w4 * cm.v.z + w5 * cm.v.w
            + w6 * nx.v.y + w7 * nx.v.z + w8 * nx.v.w;
        a.w = w0 * pm.v.z + w1 * pm.v.w + w2 * pm.R
            + w3 * cm.v.z + w4 * cm.v.w + w5 * cm.R
            + w6 * nx.v.z + w7 * nx.v.w + w8 * nx.R;
        int o = y * (W / 4) + lane;
        __stcs(&lo4[o], a);
        float4 hv;
        hv.x = cm.v.x - a.x;
        hv.y = cm.v.y - a.y;
        hv.z = cm.v.z - a.z;
        hv.w = cm.v.w - a.w;
        __stcs(&hi4[o], hv);
        pm = cm;
        cm = nx;
        n_raw = f_raw;
    }

    // last stencil block of the sample resets the flag (graph-replay safety)
    __syncthreads();
    if (threadIdx.x == 0) {
        if (atomicAdd(&g_stcnt[n], 1u) == C - 1) {
            g_stcnt[n] = 0;
            g_ready[n] = 0u;
        }
    }
}

// ---------------------------------------------------------------------------
// Single-launch software pipeline, LEAD-sample producer head start:
// [P0][P1][P2|S0][P3|S1]...[P(n-1)|S(n-3)][S(n-2)][S(n-1)]
// Pool blocks of sample s sit >= LEAD segments (~2 waves) before stencil s.
// ---------------------------------------------------------------------------
__global__ __launch_bounds__(256) void pipeline_kernel(
    const float* __restrict__ x,
    const float* __restrict__ conv_w, const float* __restrict__ gate_w,
    const float* __restrict__ gamma,  const float* __restrict__ beta,
    const float* __restrict__ mean,   const float* __restrict__ var,
    float* __restrict__ out, long long half, int n) {
    int bid = blockIdx.x;
    int lead = (n < LEAD) ? n : LEAD;
    int role, plane;
    if (bid < lead * C) {                        // leading pool segments
        role = 0; plane = bid;
    } else {
        int q = bid - lead * C;
        int mid = (n - lead) * 2 * C;            // mixed region
        if (q < mid) {
            int seg = q / (2 * C);
            int r   = q - seg * 2 * C;
            if ((r & 1) == 0) { role = 0; plane = (seg + lead) * C + (r >> 1); }
            else              { role = 1; plane = seg * C + (r >> 1); }
        } else {                                 // trailing stencil segments
            role = 1; plane = (n - lead) * C + (q - mid);
        }
    }
    if (role == 0)
        pool_path(x, conv_w, gate_w, gamma, beta, mean, var, plane);
    else
        stencil_path(x, out, half, plane);
}

// ---------------------------------------------------------------------------
extern "C" void kernel_launch(void* const* d_in, const int* in_sizes, int n_in,
                              void* d_out, int out_size) {
    const float* x      = (const float*)d_in[0];
    const float* conv_w = (const float*)d_in[1];
    const float* gate_w = (const float*)d_in[2];
    const float* gamma  = (const float*)d_in[3];
    const float* beta   = (const float*)d_in[4];
    const float* mean   = (const float*)d_in[5];
    const float* var    = (const float*)d_in[6];
    int n = in_sizes[0] / (C * H * W);
    long long half = (long long)out_size / 2;

    pipeline_kernel<<<2 * n * C, 256>>>(x, conv_w, gate_w, gamma, beta, mean,
                                        var, (float*)d_out, half, n);
}